// round 2
// baseline (speedup 1.0000x reference)
#include <cuda_runtime.h>
#include <math.h>

// Problem constants
#define H     200
#define G4    800          // 4*H
#define W     48
#define S     2047
#define MID   1023
#define BSENT 16           // sentences per block in word LSTM
#define NCTX  128          // ceil(2047/16)
#define CH_T  1024         // steps per sentence-level chain (MID+1)

// ---------------- device scratch (no cudaMalloc allowed) ----------------
__device__ float g_WT[4][H * G4];      // [ctx_ih, ctx_hh, tgt_ih, tgt_hh] transposed [k][j]
__device__ float g_bias[2][G4];        // combined bih+bhh for ctx, tgt
__device__ float g_sent_emb[S * H];    // ctx embeddings
__device__ float g_tgt_emb[H];         // target-sentence embedding
__device__ float g_h0hist[2 * CH_T * H];   // [chain][t][H] layer-0 hidden history
__device__ float g_h1hist[2 * CH_T * H];   // [chain][t][H] layer-1 hidden history
__device__ int   g_cnt[2][2][CH_T];        // [chain][layer][t] completion counters

__device__ __forceinline__ float sigm(float x) { return 1.f / (1.f + expf(-x)); }

// ---------------- kernel 0: zero the sync counters (every replay) ----------------
__global__ void zero_cnt_kernel() {
    int i = blockIdx.x * blockDim.x + threadIdx.x;
    if (i < 2 * 2 * CH_T) ((int*)g_cnt)[i] = 0;
}

// ---------------- kernel 1: transpose word-level weights + combine biases -------
__global__ void prep_kernel(const float* ci, const float* ch,
                            const float* ti, const float* th,
                            const float* cbi, const float* cbh,
                            const float* tbi, const float* tbh) {
    int idx = blockIdx.x * blockDim.x + threadIdx.x;
    if (idx < 4 * H * G4) {
        int m = idx / (H * G4);
        int r = idx % (H * G4);
        int k = r / G4;
        int j = r % G4;
        const float* src = (m == 0) ? ci : (m == 1) ? ch : (m == 2) ? ti : th;
        g_WT[m][r] = src[j * H + k];   // coalesced write, strided read (one-time cost)
    }
    if (idx < 2 * G4) {
        int m = idx / G4, j = idx % G4;
        g_bias[m][j] = m ? (tbi[j] + tbh[j]) : (cbi[j] + cbh[j]);
    }
}

// ---------------- kernel 2: word-level LSTMs (ctx batched + tgt) -----------------
// blocks 0..127: 16 ctx sentences each. block 128: target sentence (tgt weights).
// 800 threads: thread tid owns gate row j=tid.
__global__ __launch_bounds__(G4, 1) void word_lstm_kernel(const float* __restrict__ sents) {
    extern __shared__ float sm[];
    float* xs = sm;                      // [16][200]
    float* hs = xs + BSENT * H;          // [16][200]
    float* cs = hs + BSENT * H;          // [16][200]
    float* gt = cs + BSENT * H;          // [16][800]

    const int  bx     = blockIdx.x;
    const bool is_tgt = (bx == NCTX);
    const int  s0     = is_tgt ? MID : bx * BSENT;
    const int  nb     = is_tgt ? 1 : ((S - s0) < BSENT ? (S - s0) : BSENT);

    const float* __restrict__ WTih = is_tgt ? g_WT[2] : g_WT[0];
    const float* __restrict__ WThh = is_tgt ? g_WT[3] : g_WT[1];
    const float* __restrict__ bias = is_tgt ? g_bias[1] : g_bias[0];

    const int tid = threadIdx.x;          // == gate row j
    for (int i = tid; i < BSENT * H; i += G4) { xs[i] = 0.f; hs[i] = 0.f; cs[i] = 0.f; }
    const float bj = bias[tid];
    const float* wi = WTih + tid;
    const float* wh = WThh + tid;
    __syncthreads();

    for (int t = 0; t < W; t++) {
        // stage x_t for all sentences of this block
        for (int i = tid; i < nb * H; i += G4) {
            int b = i / H, k = i % H;
            xs[b * H + k] = sents[(long)(s0 + b) * (W * H) + t * H + k];
        }
        __syncthreads();

        float acc[BSENT];
        #pragma unroll
        for (int b = 0; b < BSENT; b++) acc[b] = bj;

        // gates += Wih^T-streamed * x   (weights coalesced from L2, x broadcast from smem)
        #pragma unroll 2
        for (int k = 0; k < H; k += 4) {
            float w0 = wi[(k + 0) * G4], w1 = wi[(k + 1) * G4];
            float w2 = wi[(k + 2) * G4], w3 = wi[(k + 3) * G4];
            #pragma unroll
            for (int b = 0; b < BSENT; b++) {
                float4 xv = *(const float4*)&xs[b * H + k];
                acc[b] += w0 * xv.x + w1 * xv.y + w2 * xv.z + w3 * xv.w;
            }
        }
        // gates += Whh^T-streamed * h
        #pragma unroll 2
        for (int k = 0; k < H; k += 4) {
            float w0 = wh[(k + 0) * G4], w1 = wh[(k + 1) * G4];
            float w2 = wh[(k + 2) * G4], w3 = wh[(k + 3) * G4];
            #pragma unroll
            for (int b = 0; b < BSENT; b++) {
                float4 hv = *(const float4*)&hs[b * H + k];
                acc[b] += w0 * hv.x + w1 * hv.y + w2 * hv.z + w3 * hv.w;
            }
        }
        #pragma unroll
        for (int b = 0; b < BSENT; b++) gt[b * G4 + tid] = acc[b];
        __syncthreads();

        // elementwise cell update: 16*200 units over 800 threads
        for (int i = tid; i < BSENT * H; i += G4) {
            int b = i / H, u = i % H;
            if (b < nb) {
                float ig = sigm(gt[b * G4 + u]);
                float fg = sigm(gt[b * G4 + H + u]);
                float gg = tanhf(gt[b * G4 + 2 * H + u]);
                float og = sigm(gt[b * G4 + 3 * H + u]);
                float c  = fg * cs[b * H + u] + ig * gg;
                cs[b * H + u] = c;
                hs[b * H + u] = og * tanhf(c);
            }
        }
        __syncthreads();
    }

    if (is_tgt) {
        for (int i = tid; i < H; i += G4) g_tgt_emb[i] = hs[i];
    } else {
        for (int i = tid; i < nb * H; i += G4) {
            int b = i / H, u = i % H;
            g_sent_emb[(s0 + b) * H + u] = hs[b * H + u];
        }
    }
}

// ---------------- kernel 3: sentence-level stacked LSTM chains -------------------
// 32 blocks: chain = bid>>4 (0=prev, 1=post), layer = (bid>>3)&1, part = bid&7.
// Each block owns 25 hidden units (100 gate rows), caches its weight slice in smem,
// and cross-block-syncs via fenced counters on per-step hidden-history buffers.
#define WPITCH 404   // 400 + pad(4) -> conflict-free smem rows

__global__ __launch_bounds__(128, 1) void sent_lstm_kernel(
    const float* __restrict__ pWih, const float* __restrict__ pWhh,
    const float* __restrict__ pbih, const float* __restrict__ pbhh,
    const float* __restrict__ qWih, const float* __restrict__ qWhh,
    const float* __restrict__ qbih, const float* __restrict__ qbhh) {

    const int bid   = blockIdx.x;
    const int chain = bid >> 4;
    const int layer = (bid >> 3) & 1;
    const int part  = bid & 7;

    const float* Wih = chain ? qWih : pWih;
    const float* Whh = chain ? qWhh : pWhh;
    const float* bih = chain ? qbih : pbih;
    const float* bhh = chain ? qbhh : pbhh;

    extern __shared__ float sm[];
    float* ws   = sm;                    // [100][WPITCH]: [Wih row | Whh row | pad]
    float* xh   = ws + 100 * WPITCH;     // [400] = x(200) ++ h_prev(200)
    float* gbuf = xh + 400;              // [100]
    float* cbuf = gbuf + 100;            // [25] cell state (block-local!)
    float* bbuf = cbuf + 28;             // [100]

    const int tid = threadIdx.x;         // 128 threads

    // load this block's 100 gate rows of Wih/Whh into smem (once; reused 1024 steps)
    for (int i = tid; i < 100 * H; i += 128) {
        int rr = i / H, k = i % H;
        int r  = (rr / 25) * H + part * 25 + (rr % 25);   // gate*200 + unit
        ws[rr * WPITCH + k]     = Wih[layer * (G4 * H) + r * H + k];
        ws[rr * WPITCH + H + k] = Whh[layer * (G4 * H) + r * H + k];
    }
    if (tid < 100) {
        int r = (tid / 25) * H + part * 25 + (tid % 25);
        bbuf[tid] = bih[layer * G4 + r] + bhh[layer * G4 + r];
    }
    if (tid < 25) cbuf[tid] = 0.f;
    __syncthreads();

    float* hist_own = (layer ? g_h1hist : g_h0hist) + chain * CH_T * H;
    const float* hist_in = g_h0hist + chain * CH_T * H;

    for (int t = 0; t < CH_T; t++) {
        // wait for producers (thread 0 spins, documented fence pattern)
        if (tid == 0) {
            if (layer == 1) {
                volatile int* c = &g_cnt[chain][0][t];
                while (*c < 8) { }
            }
            if (t > 0) {
                volatile int* c = &g_cnt[chain][layer][t - 1];
                while (*c < 8) { }
            }
            __threadfence();
        }
        __syncthreads();

        // gather x_t into xh[0..199]
        if (layer == 0) {
            int sidx = chain ? (2 * MID - t) : t;     // post chain reversed
            const float* xp = (sidx == MID) ? g_tgt_emb : (g_sent_emb + sidx * H);
            for (int k = tid; k < H; k += 128) xh[k] = xp[k];
        } else {
            for (int k = tid; k < H; k += 128) xh[k] = __ldcg(&hist_in[t * H + k]);
        }
        // gather own-layer h_{t-1} into xh[200..399]
        if (t == 0) {
            for (int k = tid; k < H; k += 128) xh[H + k] = 0.f;
        } else {
            for (int k = tid; k < H; k += 128) xh[H + k] = __ldcg(&hist_own[(t - 1) * H + k]);
        }
        __syncthreads();

        // 100 gate rows, one per thread (threads 100..127 idle here)
        if (tid < 100) {
            float a0 = 0.f, a1 = 0.f, a2 = 0.f, a3 = 0.f;
            const float4* wr = (const float4*)(ws + tid * WPITCH);
            const float4* xv = (const float4*)xh;
            #pragma unroll 5
            for (int k = 0; k < 100; k++) {
                float4 w = wr[k], x = xv[k];
                a0 += w.x * x.x; a1 += w.y * x.y;
                a2 += w.z * x.z; a3 += w.w * x.w;
            }
            gbuf[tid] = bbuf[tid] + ((a0 + a1) + (a2 + a3));
        }
        __syncthreads();

        if (tid < 25) {
            float ig = sigm(gbuf[tid]);
            float fg = sigm(gbuf[25 + tid]);
            float gg = tanhf(gbuf[50 + tid]);
            float og = sigm(gbuf[75 + tid]);
            float c  = fg * cbuf[tid] + ig * gg;
            cbuf[tid] = c;
            hist_own[t * H + part * 25 + tid] = og * tanhf(c);
            __threadfence();
        }
        __syncthreads();
        if (tid == 0) atomicAdd(&g_cnt[chain][layer][t], 1);
    }
}

// ---------------- kernel 4: final projection ------------------------------------
__global__ void fc_kernel(const float* __restrict__ fc_W, const float* __restrict__ fc_b,
                          float* __restrict__ out) {
    int j = threadIdx.x;
    if (j < H) {
        const float* prevh = g_h0hist;  // placeholder, replaced below
        (void)prevh;
        const float* ph = g_h1hist + 0 * CH_T * H + (CH_T - 1) * H;
        const float* qh = g_h1hist + 1 * CH_T * H + (CH_T - 1) * H;
        float acc = fc_b[j];
        const float* wr = fc_W + j * (2 * H);
        #pragma unroll 4
        for (int k = 0; k < H; k++) acc += ph[k] * wr[k];
        #pragma unroll 4
        for (int k = 0; k < H; k++) acc += qh[k] * wr[H + k];
        out[j] = acc;
    }
}

// ---------------- launcher ------------------------------------------------------
extern "C" void kernel_launch(void* const* d_in, const int* in_sizes, int n_in,
                              void* d_out, int out_size) {
    const float* sents    = (const float*)d_in[0];
    const float* ctx_Wih  = (const float*)d_in[1];
    const float* ctx_Whh  = (const float*)d_in[2];
    const float* ctx_bih  = (const float*)d_in[3];
    const float* ctx_bhh  = (const float*)d_in[4];
    const float* tgt_Wih  = (const float*)d_in[5];
    const float* tgt_Whh  = (const float*)d_in[6];
    const float* tgt_bih  = (const float*)d_in[7];
    const float* tgt_bhh  = (const float*)d_in[8];
    const float* prev_Wih = (const float*)d_in[9];
    const float* prev_Whh = (const float*)d_in[10];
    const float* prev_bih = (const float*)d_in[11];
    const float* prev_bhh = (const float*)d_in[12];
    const float* post_Wih = (const float*)d_in[13];
    const float* post_Whh = (const float*)d_in[14];
    const float* post_bih = (const float*)d_in[15];
    const float* post_bhh = (const float*)d_in[16];
    const float* fc_W     = (const float*)d_in[17];
    const float* fc_b     = (const float*)d_in[18];

    const size_t word_smem = (size_t)(3 * BSENT * H + BSENT * G4) * sizeof(float); // 89600
    const size_t sent_smem = (size_t)(100 * WPITCH + 400 + 100 + 28 + 100) * sizeof(float); // 164112

    cudaFuncSetAttribute(word_lstm_kernel, cudaFuncAttributeMaxDynamicSharedMemorySize, (int)word_smem);
    cudaFuncSetAttribute(sent_lstm_kernel, cudaFuncAttributeMaxDynamicSharedMemorySize, (int)sent_smem);

    zero_cnt_kernel<<<8, 512>>>();
    prep_kernel<<<(4 * H * G4 + 255) / 256, 256>>>(ctx_Wih, ctx_Whh, tgt_Wih, tgt_Whh,
                                                   ctx_bih, ctx_bhh, tgt_bih, tgt_bhh);
    word_lstm_kernel<<<NCTX + 1, G4, word_smem>>>(sents);
    sent_lstm_kernel<<<32, 128, sent_smem>>>(prev_Wih, prev_Whh, prev_bih, prev_bhh,
                                             post_Wih, post_Whh, post_bih, post_bhh);
    fc_kernel<<<1, 256>>>(fc_W, fc_b, (float*)d_out);
}